// round 10
// baseline (speedup 1.0000x reference)
#include <cuda_runtime.h>
#include <cstddef>

#define BATCH_N 16384
#define SEQ_N   512
#define HID_N   5
#define FLAT_N  2560        // SEQ_N*HID_N

// Collapsed linear head: Weff = W2 @ W1 (1 x 2560), beff = W2@b1 + b2
__device__ float g_Weff[FLAT_N];
__device__ float g_beff;

// ---------------------------------------------------------------------------
// Kernel 1: collapse the two linear layers (no nonlinearity between them).
// ---------------------------------------------------------------------------
__global__ void weff_kernel(const float* __restrict__ W1,
                            const float* __restrict__ b1,
                            const float* __restrict__ W2,
                            const float* __restrict__ b2)
{
    int j = blockIdx.x * blockDim.x + threadIdx.x;
    if (j < FLAT_N) {
        float acc = 0.0f;
        #pragma unroll 8
        for (int k = 0; k < 512; ++k)
            acc = fmaf(W2[k], W1[(size_t)k * FLAT_N + j], acc);
        g_Weff[j] = acc;
    }
    if (j == 0) {
        float acc = b2[0];
        for (int k = 0; k < 512; ++k)
            acc = fmaf(W2[k], b1[k], acc);
        g_beff = acc;
    }
}

// ---------------------------------------------------------------------------
// Packed f32x2 + fast-activation primitives
// ---------------------------------------------------------------------------
typedef unsigned long long u64;

__device__ __forceinline__ u64 pack2(float lo, float hi) {
    u64 r; asm("mov.b64 %0, {%1, %2};" : "=l"(r) : "f"(lo), "f"(hi)); return r;
}
__device__ __forceinline__ void unpack2(u64 v, float& lo, float& hi) {
    asm("mov.b64 {%0, %1}, %2;" : "=f"(lo), "=f"(hi) : "l"(v));
}
__device__ __forceinline__ u64 fma2(u64 a, u64 b, u64 c) {
    u64 d; asm("fma.rn.f32x2 %0, %1, %2, %3;" : "=l"(d) : "l"(a), "l"(b), "l"(c)); return d;
}
__device__ __forceinline__ u64 mul2(u64 a, u64 b) {
    u64 d; asm("mul.rn.f32x2 %0, %1, %2;" : "=l"(d) : "l"(a), "l"(b)); return d;
}
__device__ __forceinline__ float tanh_fast(float x) {
    float y; asm("tanh.approx.f32 %0, %1;" : "=f"(y) : "f"(x)); return y;
}
__device__ __forceinline__ float sig_fast(float x) {
    return fmaf(0.5f, tanh_fast(0.5f * x), 0.5f);
}

// ---------------------------------------------------------------------------
// Kernel 2: TWO threads per batch element (round-7 layout) with a deeper
// software pipeline:
//   * layer-0 gate chains for step s+1 overlap layer-1 work of step s
//   * layer-1's recurrent half  ga1p = B1 + Whh1@h1(s)  is computed right
//     after the h1 exchange, so the post-h0-exchange serial segment is only
//     the 5-fma Wih1@h0 chain.
// Register budget: B1+Whh1 (42 u64) in regs; Wih1 (30 u64) via LDS.128.
// ---------------------------------------------------------------------------
__global__ void __launch_bounds__(256)
lstm_fused_kernel(const float* __restrict__ x,
                  const float* __restrict__ Wih0, const float* __restrict__ Whh0,
                  const float* __restrict__ bih0, const float* __restrict__ bhh0,
                  const float* __restrict__ Wih1, const float* __restrict__ Whh1,
                  const float* __restrict__ bih1, const float* __restrict__ bhh1,
                  float* __restrict__ out)
{
    __shared__ __align__(16) u64 sL0[2][6][8];    // B0, Wih0, Whh0 c0..c4, pad
    __shared__ __align__(16) u64 sW1i[2][6][8];   // Wih1 c0..c4, pad (LDS path)
    __shared__ __align__(16) u64 sW1r[2][6][8];   // B1, Whh1 c0..c4, pad (hoisted)
    __shared__ __align__(16) u64 sWeffP[2][SEQ_N];
    __shared__ float sWeffS[2][SEQ_N];

    const int t = threadIdx.x;

    // ---- build role-specialized packed weight tables ----
    if (t < 12) {
        const int r = t / 6, p = t % 6;
        const int q = p >> 1;                       // unit slot 0..2
        const int j = (r == 0) ? q : q + 2;         // unit id: lo {0,1,2}, hi {2,3,4}
        int rowA, rowB;
        if ((p & 1) == 0) { rowA = j;      rowB = 5 + j;  }   // (i_j, f_j)
        else              { rowA = 10 + j; rowB = 15 + j; }   // (g_j, o_j)

        sL0[r][p][0]  = pack2(bih0[rowA] + bhh0[rowA], bih0[rowB] + bhh0[rowB]);
        sL0[r][p][1]  = pack2(Wih0[rowA], Wih0[rowB]);
        sW1r[r][p][0] = pack2(bih1[rowA] + bhh1[rowA], bih1[rowB] + bhh1[rowB]);
        #pragma unroll
        for (int k = 0; k < HID_N; ++k) {
            const int c = (r == 0) ? k : (k + 2) % HID_N;   // column permutation
            sL0[r][p][2 + k]  = pack2(Whh0[rowA * HID_N + c], Whh0[rowB * HID_N + c]);
            sW1i[r][p][k]     = pack2(Wih1[rowA * HID_N + c], Wih1[rowB * HID_N + c]);
            sW1r[r][p][1 + k] = pack2(Whh1[rowA * HID_N + c], Whh1[rowB * HID_N + c]);
        }
        sL0[r][p][7]  = 0ull;
        sW1i[r][p][5] = 0ull; sW1i[r][p][6] = 0ull; sW1i[r][p][7] = 0ull;
        sW1r[r][p][6] = 0ull; sW1r[r][p][7] = 0ull;
    }
    for (int s = t; s < SEQ_N; s += blockDim.x) {
        sWeffP[0][s] = pack2(g_Weff[5 * s + 0], g_Weff[5 * s + 1]);
        sWeffP[1][s] = pack2(g_Weff[5 * s + 2], g_Weff[5 * s + 3]);
        sWeffS[0][s] = 0.0f;
        sWeffS[1][s] = g_Weff[5 * s + 4];
    }
    __syncthreads();

    const int gid = blockIdx.x * blockDim.x + t;
    const int e   = gid >> 1;          // batch element
    const int r   = gid & 1;           // role
    const float4* __restrict__ xr4 = (const float4*)(x + (size_t)e * SEQ_N);

    const u64 (*__restrict__ L0)[8]  = sL0[r];
    const u64 (*__restrict__ W1I)[8] = sW1i[r];
    const u64*   __restrict__ WfP    = sWeffP[r];
    const float* __restrict__ WfS    = sWeffS[r];

    // ---- hoist B1 + Whh1 into registers (42 u64 = 84 regs) ----
    u64 w1B[6], w1H[6][HID_N];
    {
        const u64 (*__restrict__ W1R)[8] = sW1r[r];
        #pragma unroll
        for (int p = 0; p < 6; ++p) {
            w1B[p] = W1R[p][0];
            #pragma unroll
            for (int k = 0; k < HID_N; ++k)
                w1H[p][k] = W1R[p][1 + k];
        }
    }

    const u64 HALF2 = pack2(0.5f, 0.5f);

    u64 h0v[HID_N], h1v[HID_N];
    float c0[3], c1[3];
    #pragma unroll
    for (int k = 0; k < HID_N; ++k) { h0v[k] = 0ull; h1v[k] = 0ull; }
    #pragma unroll
    for (int q = 0; q < 3; ++q) { c0[q] = 0.f; c1[q] = 0.f; }

    u64 acc2 = 0ull;
    float accS = 0.0f;

    auto l0_chains = [&](u64* ga, u64 xx) {
        #pragma unroll
        for (int p = 0; p < 6; ++p) {
            u64 a = fma2(L0[p][1], xx, L0[p][0]);
            #pragma unroll
            for (int k = 0; k < HID_N; ++k)
                a = fma2(L0[p][2 + k], h0v[k], a);
            ga[p] = a;
        }
    };

    // ---- prologue: step-0 layer-0 gates (h0v==0) and ga1p = B1 (h1v==0) ----
    float4 xq = __ldg(&xr4[0]);
    u64 ga0[6], ga1p[6];
    l0_chains(ga0, pack2(xq.x, xq.x));
    #pragma unroll
    for (int p = 0; p < 6; ++p) ga1p[p] = w1B[p];

    #pragma unroll 1
    for (int s4 = 0; s4 < SEQ_N / 4; ++s4) {
        float4 xq_next;
        if (s4 + 1 < SEQ_N / 4) xq_next = __ldg(&xr4[s4 + 1]);
        else                    xq_next = make_float4(0.f, 0.f, 0.f, 0.f);

        #pragma unroll
        for (int su = 0; su < 4; ++su) {
            const int s = 4 * s4 + su;
            const float xn = (su == 0) ? xq.y : (su == 1) ? xq.z
                           : (su == 2) ? xq.w : xq_next.x;

            // ---- layer 0 activations for step s (pipelined ga0) ----
            float hu[3];
            #pragma unroll
            for (int q = 0; q < 3; ++q) {
                float iv, fv, gv, ov, ig, fg;
                unpack2(mul2(ga0[2 * q], HALF2), iv, fv);
                float ti = tanh_fast(iv), tf = tanh_fast(fv);
                unpack2(fma2(pack2(ti, tf), HALF2, HALF2), ig, fg);
                unpack2(ga0[2 * q + 1], gv, ov);
                float gg = tanh_fast(gv);
                float og = sig_fast(ov);
                float c = fmaf(fg, c0[q], ig * gg);
                c0[q] = c;
                hu[q] = og * tanh_fast(c);
            }
            // ---- exchange h0 ----
            {
                float sA = r ? hu[1] : hu[0];
                float sB = r ? hu[2] : hu[1];
                float ra = __shfl_xor_sync(0xffffffffu, sA, 1);
                float rb = __shfl_xor_sync(0xffffffffu, sB, 1);
                h0v[0] = pack2(hu[0], hu[0]);
                h0v[1] = pack2(hu[1], hu[1]);
                h0v[2] = pack2(hu[2], hu[2]);
                h0v[3] = pack2(ra, ra);
                h0v[4] = pack2(rb, rb);
            }

            // ---- layer 1 gates: only the 5-fma Wih1@h0 half is serial now ----
            u64 ga1[6];
            #pragma unroll
            for (int p = 0; p < 6; ++p) {
                u64 a = ga1p[p];
                #pragma unroll
                for (int k = 0; k < HID_N; ++k)
                    a = fma2(W1I[p][k], h0v[k], a);
                ga1[p] = a;
            }

            // ---- PIPELINE: layer-0 chains for step s+1 (fills stalls) ----
            u64 ga0n[6];
            l0_chains(ga0n, pack2(xn, xn));

            // ---- layer 1 activations ----
            #pragma unroll
            for (int q = 0; q < 3; ++q) {
                float iv, fv, gv, ov, ig, fg;
                unpack2(mul2(ga1[2 * q], HALF2), iv, fv);
                float ti = tanh_fast(iv), tf = tanh_fast(fv);
                unpack2(fma2(pack2(ti, tf), HALF2, HALF2), ig, fg);
                unpack2(ga1[2 * q + 1], gv, ov);
                float gg = tanh_fast(gv);
                float og = sig_fast(ov);
                float c = fmaf(fg, c1[q], ig * gg);
                c1[q] = c;
                hu[q] = og * tanh_fast(c);
            }
            // ---- folded head ----
            acc2 = fma2(pack2(hu[0], hu[1]), WfP[s], acc2);
            accS = fmaf(hu[2], WfS[s], accS);

            // ---- exchange h1 ----
            {
                float sA = r ? hu[1] : hu[0];
                float sB = r ? hu[2] : hu[1];
                float ra = __shfl_xor_sync(0xffffffffu, sA, 1);
                float rb = __shfl_xor_sync(0xffffffffu, sB, 1);
                h1v[0] = pack2(hu[0], hu[0]);
                h1v[1] = pack2(hu[1], hu[1]);
                h1v[2] = pack2(hu[2], hu[2]);
                h1v[3] = pack2(ra, ra);
                h1v[4] = pack2(rb, rb);
            }

            // ---- PIPELINE: recurrent half of next step's layer-1 gates ----
            #pragma unroll
            for (int p = 0; p < 6; ++p) {
                u64 a = w1B[p];
                #pragma unroll
                for (int k = 0; k < HID_N; ++k)
                    a = fma2(w1H[p][k], h1v[k], a);
                ga1p[p] = a;
            }

            // rotate layer-0 pipeline register
            #pragma unroll
            for (int p = 0; p < 6; ++p) ga0[p] = ga0n[p];
        }
        xq = xq_next;
    }

    // combine the two partial head sums; role 0 writes
    float alo, ahi;
    unpack2(acc2, alo, ahi);
    float part = accS + alo + ahi;
    float tot  = part + __shfl_xor_sync(0xffffffffu, part, 1);
    if (r == 0)
        out[e] = tot + g_beff;
}

// ---------------------------------------------------------------------------
// Harness entry. Inputs in metadata order:
// x, Wih0, Whh0, bih0, bhh0, Wih1, Whh1, bih1, bhh1, W1, b1, W2, b2
// ---------------------------------------------------------------------------
extern "C" void kernel_launch(void* const* d_in, const int* in_sizes, int n_in,
                              void* d_out, int out_size)
{
    const float* x    = (const float*)d_in[0];
    const float* Wih0 = (const float*)d_in[1];
    const float* Whh0 = (const float*)d_in[2];
    const float* bih0 = (const float*)d_in[3];
    const float* bhh0 = (const float*)d_in[4];
    const float* Wih1 = (const float*)d_in[5];
    const float* Whh1 = (const float*)d_in[6];
    const float* bih1 = (const float*)d_in[7];
    const float* bhh1 = (const float*)d_in[8];
    const float* W1   = (const float*)d_in[9];
    const float* b1   = (const float*)d_in[10];
    const float* W2   = (const float*)d_in[11];
    const float* b2   = (const float*)d_in[12];
    float* out = (float*)d_out;

    weff_kernel<<<(FLAT_N + 511) / 512, 512>>>(W1, b1, W2, b2);

    // 32768 threads: 2 per batch element, 256/block -> 128 blocks (2 warps/SMSP)
    lstm_fused_kernel<<<(BATCH_N * 2) / 256, 256>>>(x, Wih0, Whh0, bih0, bhh0,
                                                    Wih1, Whh1, bih1, bhh1, out);
}

// round 11
// speedup vs baseline: 1.1134x; 1.1134x over previous
#include <cuda_runtime.h>
#include <cstddef>

#define BATCH_N 16384
#define SEQ_N   512
#define HID_N   5
#define FLAT_N  2560        // SEQ_N*HID_N
#define TPB     640         // 20 warps = 5 warps/SMSP
#define EPW     6           // elements per warp (lanes 0-29; 30,31 idle)
#define EPB     120         // elements per block = 20 warps * 6

// Collapsed linear head: Weff = W2 @ W1 (1 x 2560), beff = W2@b1 + b2
__device__ float g_Weff[FLAT_N];
__device__ float g_beff;

// ---------------------------------------------------------------------------
// Kernel 1: collapse the two linear layers (no nonlinearity between them).
// ---------------------------------------------------------------------------
__global__ void weff_kernel(const float* __restrict__ W1,
                            const float* __restrict__ b1,
                            const float* __restrict__ W2,
                            const float* __restrict__ b2)
{
    int j = blockIdx.x * blockDim.x + threadIdx.x;
    if (j < FLAT_N) {
        float acc = 0.0f;
        #pragma unroll 8
        for (int k = 0; k < 512; ++k)
            acc = fmaf(W2[k], W1[(size_t)k * FLAT_N + j], acc);
        g_Weff[j] = acc;
    }
    if (j == 0) {
        float acc = b2[0];
        for (int k = 0; k < 512; ++k)
            acc = fmaf(W2[k], b1[k], acc);
        g_beff = acc;
    }
}

// ---------------------------------------------------------------------------
// Packed f32x2 + fast-activation primitives
// ---------------------------------------------------------------------------
typedef unsigned long long u64;

__device__ __forceinline__ u64 pack2(float lo, float hi) {
    u64 r; asm("mov.b64 %0, {%1, %2};" : "=l"(r) : "f"(lo), "f"(hi)); return r;
}
__device__ __forceinline__ void unpack2(u64 v, float& lo, float& hi) {
    asm("mov.b64 {%0, %1}, %2;" : "=f"(lo), "=f"(hi) : "l"(v));
}
__device__ __forceinline__ u64 fma2(u64 a, u64 b, u64 c) {
    u64 d; asm("fma.rn.f32x2 %0, %1, %2, %3;" : "=l"(d) : "l"(a), "l"(b), "l"(c)); return d;
}
__device__ __forceinline__ float tanh_fast(float x) {
    float y; asm("tanh.approx.f32 %0, %1;" : "=f"(y) : "f"(x)); return y;
}

// ---------------------------------------------------------------------------
// Kernel 2: FIVE threads per batch element. Lane group g = [5g, 5g+5) owns one
// element; thread with role u owns hidden unit u in both layers (no
// duplication -> 10 tanh/step/thread, the MUFU floor minimum).
//   Gate pairs per unit: (i,f) and (g,o). Sigmoid pre-scale 0.5 is folded into
//   the weight/bias tables for rows i, f, o, so activations need no input mul.
// Layer-1 weights (22 u64) register-resident. Layer-0 (14 u64) via padded,
// conflict-free LDS.128 (role stride 144 B). h exchange: 5 shfls per layer.
// ---------------------------------------------------------------------------
__global__ void __launch_bounds__(TPB, 1)
lstm_fused_kernel(const float* __restrict__ x,
                  const float* __restrict__ Wih0, const float* __restrict__ Whh0,
                  const float* __restrict__ bih0, const float* __restrict__ bhh0,
                  const float* __restrict__ Wih1, const float* __restrict__ Whh1,
                  const float* __restrict__ bih1, const float* __restrict__ bhh1,
                  float* __restrict__ out)
{
    // L0: role stride 18 u64 (=144B, conflict-free); pair p at +8p, slots:
    //   0=B, 1=Wih, 2..6=Whh c0..c4, 7=pad
    __shared__ __align__(16) u64 sL0[5 * 18];
    // L1 staging (copied to regs): [role][pair][0=B,1..5=Wih1,6..10=Whh1]
    __shared__ __align__(16) u64 sL1[5][2][11];
    // Head weights: sWf[u][s] = Weff[5s+u]; row stride 513 (conflict-free)
    __shared__ float sWf[5][SEQ_N + 1];

    const int t = threadIdx.x;

    // ---- build tables (10 builder threads: role u, pair p) ----
    if (t < 10) {
        const int u = t >> 1, p = t & 1;
        const int rowA = (p == 0) ? u : 10 + u;        // i or g
        const int rowB = (p == 0) ? 5 + u : 15 + u;    // f or o
        const float sA = (p == 0) ? 0.5f : 1.0f;       // i scaled, g not
        const float sB = 0.5f;                          // f, o scaled

        u64* L0 = &sL0[u * 18 + p * 8];
        L0[0] = pack2(sA * (bih0[rowA] + bhh0[rowA]), sB * (bih0[rowB] + bhh0[rowB]));
        L0[1] = pack2(sA * Wih0[rowA], sB * Wih0[rowB]);
        sL1[u][p][0] = pack2(sA * (bih1[rowA] + bhh1[rowA]), sB * (bih1[rowB] + bhh1[rowB]));
        #pragma unroll
        for (int k = 0; k < HID_N; ++k) {
            L0[2 + k]        = pack2(sA * Whh0[rowA * HID_N + k], sB * Whh0[rowB * HID_N + k]);
            sL1[u][p][1 + k] = pack2(sA * Wih1[rowA * HID_N + k], sB * Wih1[rowB * HID_N + k]);
            sL1[u][p][6 + k] = pack2(sA * Whh1[rowA * HID_N + k], sB * Whh1[rowB * HID_N + k]);
        }
        L0[7] = 0ull;
    }
    for (int i = t; i < HID_N * SEQ_N; i += TPB) {
        const int u = i / SEQ_N, s = i - u * SEQ_N;
        sWf[u][s] = g_Weff[5 * s + u];
    }
    __syncthreads();

    const int lane  = t & 31;
    const int warp  = t >> 5;
    const int group = lane / 5;                 // 0..5 real, 6 = lanes 30,31
    const int u     = lane - group * 5;         // role / owned unit
    const int baseL = group * 5;

    const int  e_raw = blockIdx.x * EPB + warp * EPW + group;
    const bool valid = (group < EPW) && (e_raw < BATCH_N);
    const int  e     = valid ? e_raw : 0;

    const float4* __restrict__ xr4 = (const float4*)(x + (size_t)e * SEQ_N);
    const u64* __restrict__ L0 = &sL0[u * 18];
    const float* __restrict__ Wfr = sWf[u];

    // ---- hoist layer-1 weights into registers (22 u64 = 44 regs) ----
    u64 w1[2][11];
    #pragma unroll
    for (int p = 0; p < 2; ++p)
        #pragma unroll
        for (int k = 0; k < 11; ++k)
            w1[p][k] = sL1[u][p][k];

    const u64 HALF2 = pack2(0.5f, 0.5f);

    u64 h0v[HID_N], h1v[HID_N];                 // broadcast-packed full h
    float c0 = 0.f, c1 = 0.f;                   // own unit's cell state
    #pragma unroll
    for (int k = 0; k < HID_N; ++k) { h0v[k] = 0ull; h1v[k] = 0ull; }

    float accS = 0.0f;

    #pragma unroll 1
    for (int s4 = 0; s4 < SEQ_N / 4; ++s4) {
        const float4 xq = __ldg(&xr4[s4]);

        #pragma unroll
        for (int su = 0; su < 4; ++su) {
            const int s = 4 * s4 + su;
            const float xin = (su == 0) ? xq.x : (su == 1) ? xq.y : (su == 2) ? xq.z : xq.w;
            const u64 xx = pack2(xin, xin);

            // ---- layer 0: 2 packed gate-pair chains (LDS.128 weights) ----
            u64 ga = fma2(L0[1], xx, L0[0]);
            u64 gb = fma2(L0[9], xx, L0[8]);
            #pragma unroll
            for (int k = 0; k < HID_N; ++k) {
                ga = fma2(L0[2 + k],  h0v[k], ga);
                gb = fma2(L0[10 + k], h0v[k], gb);
            }
            // ---- layer 0 activation (own unit; i,f,o pre-scaled) ----
            float h0u;
            {
                float iv, fv, gv, ov, ig, fg;
                unpack2(ga, iv, fv);
                float ti = tanh_fast(iv), tf = tanh_fast(fv);
                unpack2(fma2(pack2(ti, tf), HALF2, HALF2), ig, fg);
                unpack2(gb, gv, ov);
                float gg = tanh_fast(gv);
                float og = fmaf(0.5f, tanh_fast(ov), 0.5f);
                float c  = fmaf(fg, c0, ig * gg);
                c0 = c;
                h0u = og * tanh_fast(c);
            }
            // ---- exchange full h0: 5 computed-lane shfls ----
            {
                float a0 = __shfl_sync(0xffffffffu, h0u, baseL);
                float a1 = __shfl_sync(0xffffffffu, h0u, baseL + 1);
                float a2 = __shfl_sync(0xffffffffu, h0u, baseL + 2);
                float a3 = __shfl_sync(0xffffffffu, h0u, baseL + 3);
                float a4 = __shfl_sync(0xffffffffu, h0u, baseL + 4);
                h0v[0] = pack2(a0, a0);
                h0v[1] = pack2(a1, a1);
                h0v[2] = pack2(a2, a2);
                h0v[3] = pack2(a3, a3);
                h0v[4] = pack2(a4, a4);
            }

            // ---- layer 1: 2 packed chains, register weights ----
            u64 gc = fma2(w1[0][1], h0v[0], w1[0][0]);
            u64 gd = fma2(w1[1][1], h0v[0], w1[1][0]);
            #pragma unroll
            for (int k = 1; k < HID_N; ++k) {
                gc = fma2(w1[0][1 + k], h0v[k], gc);
                gd = fma2(w1[1][1 + k], h0v[k], gd);
            }
            #pragma unroll
            for (int k = 0; k < HID_N; ++k) {
                gc = fma2(w1[0][6 + k], h1v[k], gc);
                gd = fma2(w1[1][6 + k], h1v[k], gd);
            }
            // ---- layer 1 activation ----
            float h1u;
            {
                float iv, fv, gv, ov, ig, fg;
                unpack2(gc, iv, fv);
                float ti = tanh_fast(iv), tf = tanh_fast(fv);
                unpack2(fma2(pack2(ti, tf), HALF2, HALF2), ig, fg);
                unpack2(gd, gv, ov);
                float gg = tanh_fast(gv);
                float og = fmaf(0.5f, tanh_fast(ov), 0.5f);
                float c  = fmaf(fg, c1, ig * gg);
                c1 = c;
                h1u = og * tanh_fast(c);
            }
            // ---- folded head: own unit only ----
            accS = fmaf(h1u, Wfr[s], accS);

            // ---- exchange full h1 ----
            {
                float a0 = __shfl_sync(0xffffffffu, h1u, baseL);
                float a1 = __shfl_sync(0xffffffffu, h1u, baseL + 1);
                float a2 = __shfl_sync(0xffffffffu, h1u, baseL + 2);
                float a3 = __shfl_sync(0xffffffffu, h1u, baseL + 3);
                float a4 = __shfl_sync(0xffffffffu, h1u, baseL + 4);
                h1v[0] = pack2(a0, a0);
                h1v[1] = pack2(a1, a1);
                h1v[2] = pack2(a2, a2);
                h1v[3] = pack2(a3, a3);
                h1v[4] = pack2(a4, a4);
            }
        }
    }

    // ---- combine the 5 role partials; role 0 of each valid group writes ----
    float p0 = __shfl_sync(0xffffffffu, accS, baseL);
    float p1 = __shfl_sync(0xffffffffu, accS, baseL + 1);
    float p2 = __shfl_sync(0xffffffffu, accS, baseL + 2);
    float p3 = __shfl_sync(0xffffffffu, accS, baseL + 3);
    float p4 = __shfl_sync(0xffffffffu, accS, baseL + 4);
    if (u == 0 && valid)
        out[e] = ((p0 + p1) + (p2 + p3)) + p4 + g_beff;
}

// ---------------------------------------------------------------------------
// Harness entry. Inputs in metadata order:
// x, Wih0, Whh0, bih0, bhh0, Wih1, Whh1, bih1, bhh1, W1, b1, W2, b2
// ---------------------------------------------------------------------------
extern "C" void kernel_launch(void* const* d_in, const int* in_sizes, int n_in,
                              void* d_out, int out_size)
{
    const float* x    = (const float*)d_in[0];
    const float* Wih0 = (const float*)d_in[1];
    const float* Whh0 = (const float*)d_in[2];
    const float* bih0 = (const float*)d_in[3];
    const float* bhh0 = (const float*)d_in[4];
    const float* Wih1 = (const float*)d_in[5];
    const float* Whh1 = (const float*)d_in[6];
    const float* bih1 = (const float*)d_in[7];
    const float* bhh1 = (const float*)d_in[8];
    const float* W1   = (const float*)d_in[9];
    const float* b1   = (const float*)d_in[10];
    const float* W2   = (const float*)d_in[11];
    const float* b2   = (const float*)d_in[12];
    float* out = (float*)d_out;

    weff_kernel<<<(FLAT_N + 511) / 512, 512>>>(W1, b1, W2, b2);

    // 5 threads/element, 640-thread blocks (20 warps = 5/SMSP), 120 elems/block
    const int nblocks = (BATCH_N + EPB - 1) / EPB;   // 137 <= 148 SMs, one wave
    lstm_fused_kernel<<<nblocks, TPB>>>(x, Wih0, Whh0, bih0, bhh0,
                                        Wih1, Whh1, bih1, bhh1, out);
}

// round 13
// speedup vs baseline: 1.2003x; 1.0780x over previous
#include <cuda_runtime.h>
#include <cstddef>

#define BATCH_N 16384
#define SEQ_N   512
#define HID_N   5
#define FLAT_N  2560        // SEQ_N*HID_N
#define TPB     640         // 20 warps = 5 warps/SMSP
#define EPW     6           // elements per warp (lanes 0-29; 30,31 idle)
#define EPB     120         // elements per block = 20 warps * 6

// Collapsed linear head: Weff = W2 @ W1 (1 x 2560), beff = W2@b1 + b2
__device__ float g_Weff[FLAT_N];
__device__ float g_beff;

// ---------------------------------------------------------------------------
// Kernel 1: collapse the two linear layers (no nonlinearity between them).
// ---------------------------------------------------------------------------
__global__ void weff_kernel(const float* __restrict__ W1,
                            const float* __restrict__ b1,
                            const float* __restrict__ W2,
                            const float* __restrict__ b2)
{
    int j = blockIdx.x * blockDim.x + threadIdx.x;
    if (j < FLAT_N) {
        float acc = 0.0f;
        #pragma unroll 8
        for (int k = 0; k < 512; ++k)
            acc = fmaf(W2[k], W1[(size_t)k * FLAT_N + j], acc);
        g_Weff[j] = acc;
    }
    if (j == 0) {
        float acc = b2[0];
        for (int k = 0; k < 512; ++k)
            acc = fmaf(W2[k], b1[k], acc);
        g_beff = acc;
    }
}

// ---------------------------------------------------------------------------
// Packed f32x2 + fast-activation primitives
// ---------------------------------------------------------------------------
typedef unsigned long long u64;

__device__ __forceinline__ u64 pack2(float lo, float hi) {
    u64 r; asm("mov.b64 %0, {%1, %2};" : "=l"(r) : "f"(lo), "f"(hi)); return r;
}
__device__ __forceinline__ void unpack2(u64 v, float& lo, float& hi) {
    asm("mov.b64 {%0, %1}, %2;" : "=f"(lo), "=f"(hi) : "l"(v));
}
__device__ __forceinline__ u64 fma2(u64 a, u64 b, u64 c) {
    u64 d; asm("fma.rn.f32x2 %0, %1, %2, %3;" : "=l"(d) : "l"(a), "l"(b), "l"(c)); return d;
}
__device__ __forceinline__ float tanh_fast(float x) {
    float y; asm("tanh.approx.f32 %0, %1;" : "=f"(y) : "f"(x)); return y;
}

// ---------------------------------------------------------------------------
// Kernel 2: FIVE threads per batch element; thread role u owns hidden unit u
// in both layers (10 tanh/step/thread = MUFU minimum for this split).
//   * sigmoid pre-scale 0.5 folded into i/f/o weight rows
//   * layer-1 weights (22 u64) register-resident; layer-0 via padded LDS.128
//   * SPLIT layer-1 chain: ga1p = B1 + Whh1@h1(s) is computed right after the
//     h1 exchange, so only the 5-fma2 Wih1@h0 half sits on the serial path
//   * head weights read as one float4 per 4 steps
// ---------------------------------------------------------------------------
__global__ void __launch_bounds__(TPB, 1)
lstm_fused_kernel(const float* __restrict__ x,
                  const float* __restrict__ Wih0, const float* __restrict__ Whh0,
                  const float* __restrict__ bih0, const float* __restrict__ bhh0,
                  const float* __restrict__ Wih1, const float* __restrict__ Whh1,
                  const float* __restrict__ bih1, const float* __restrict__ bhh1,
                  float* __restrict__ out)
{
    // L0: role stride 18 u64 (=144B, conflict-free); pair p at +8p, slots:
    //   0=B, 1=Wih, 2..6=Whh c0..c4, 7=pad
    __shared__ __align__(16) u64 sL0[5 * 18];
    // L1 staging (copied to regs): [role][pair][0=B,1..5=Wih1,6..10=Whh1]
    __shared__ __align__(16) u64 sL1[5][2][11];
    // Head weights, float4 per 4 steps: sWf4[u][s4] = Weff[5*(4s4+j)+u], j=0..3
    __shared__ __align__(16) float4 sWf4[5][SEQ_N / 4];

    const int t = threadIdx.x;

    // ---- build tables (10 builder threads: role u, pair p) ----
    if (t < 10) {
        const int u = t >> 1, p = t & 1;
        const int rowA = (p == 0) ? u : 10 + u;        // i or g
        const int rowB = (p == 0) ? 5 + u : 15 + u;    // f or o
        const float sA = (p == 0) ? 0.5f : 1.0f;       // i scaled, g not
        const float sB = 0.5f;                          // f, o scaled

        u64* L0 = &sL0[u * 18 + p * 8];
        L0[0] = pack2(sA * (bih0[rowA] + bhh0[rowA]), sB * (bih0[rowB] + bhh0[rowB]));
        L0[1] = pack2(sA * Wih0[rowA], sB * Wih0[rowB]);
        sL1[u][p][0] = pack2(sA * (bih1[rowA] + bhh1[rowA]), sB * (bih1[rowB] + bhh1[rowB]));
        #pragma unroll
        for (int k = 0; k < HID_N; ++k) {
            L0[2 + k]        = pack2(sA * Whh0[rowA * HID_N + k], sB * Whh0[rowB * HID_N + k]);
            sL1[u][p][1 + k] = pack2(sA * Wih1[rowA * HID_N + k], sB * Wih1[rowB * HID_N + k]);
            sL1[u][p][6 + k] = pack2(sA * Whh1[rowA * HID_N + k], sB * Whh1[rowB * HID_N + k]);
        }
        L0[7] = 0ull;
    }
    for (int i = t; i < HID_N * (SEQ_N / 4); i += TPB) {
        const int u = i / (SEQ_N / 4), s4 = i - u * (SEQ_N / 4);
        sWf4[u][s4] = make_float4(g_Weff[5 * (4 * s4 + 0) + u],
                                  g_Weff[5 * (4 * s4 + 1) + u],
                                  g_Weff[5 * (4 * s4 + 2) + u],
                                  g_Weff[5 * (4 * s4 + 3) + u]);
    }
    __syncthreads();

    const int lane  = t & 31;
    const int warp  = t >> 5;
    const int group = lane / 5;                 // 0..5 real, 6 = lanes 30,31
    const int u     = lane - group * 5;         // role / owned unit
    const int baseL = group * 5;

    const int  e_raw = blockIdx.x * EPB + warp * EPW + group;
    const bool valid = (group < EPW) && (e_raw < BATCH_N);
    const int  e     = valid ? e_raw : 0;

    const float4* __restrict__ xr4  = (const float4*)(x + (size_t)e * SEQ_N);
    const u64*    __restrict__ L0   = &sL0[u * 18];
    const float4* __restrict__ Wfr4 = sWf4[u];

    // ---- hoist layer-1 weights into registers (22 u64 = 44 regs) ----
    u64 w1[2][11];
    #pragma unroll
    for (int p = 0; p < 2; ++p)
        #pragma unroll
        for (int k = 0; k < 11; ++k)
            w1[p][k] = sL1[u][p][k];

    const u64 HALF2 = pack2(0.5f, 0.5f);

    u64 h0v[HID_N], h1v[HID_N];                 // broadcast-packed full h
    float c0 = 0.f, c1 = 0.f;                   // own unit's cell state
    #pragma unroll
    for (int k = 0; k < HID_N; ++k) { h0v[k] = 0ull; h1v[k] = 0ull; }

    // SPLIT-CHAIN pipeline regs: recurrent half of layer-1 gates (h1v==0 -> B1)
    u64 ga1p0 = w1[0][0];
    u64 ga1p1 = w1[1][0];

    float accS = 0.0f;

    #pragma unroll 1
    for (int s4 = 0; s4 < SEQ_N / 4; ++s4) {
        const float4 xq = __ldg(&xr4[s4]);
        const float4 wq = Wfr4[s4];             // 4 head weights, one LDS.128

        #pragma unroll
        for (int su = 0; su < 4; ++su) {
            const float xin = (su == 0) ? xq.x : (su == 1) ? xq.y : (su == 2) ? xq.z : xq.w;
            const float wfs = (su == 0) ? wq.x : (su == 1) ? wq.y : (su == 2) ? wq.z : wq.w;
            const u64 xx = pack2(xin, xin);

            // ---- layer 0: 2 packed gate-pair chains (LDS.128 weights) ----
            u64 ga = fma2(L0[1], xx, L0[0]);
            u64 gb = fma2(L0[9], xx, L0[8]);
            #pragma unroll
            for (int k = 0; k < HID_N; ++k) {
                ga = fma2(L0[2 + k],  h0v[k], ga);
                gb = fma2(L0[10 + k], h0v[k], gb);
            }
            // ---- layer 0 activation (own unit; i,f,o pre-scaled) ----
            float h0u;
            {
                float iv, fv, gv, ov, ig, fg;
                unpack2(ga, iv, fv);
                float ti = tanh_fast(iv), tf = tanh_fast(fv);
                unpack2(fma2(pack2(ti, tf), HALF2, HALF2), ig, fg);
                unpack2(gb, gv, ov);
                float gg = tanh_fast(gv);
                float og = fmaf(0.5f, tanh_fast(ov), 0.5f);
                float c  = fmaf(fg, c0, ig * gg);
                c0 = c;
                h0u = og * tanh_fast(c);
            }
            // ---- exchange full h0: 5 computed-lane shfls ----
            {
                float a0 = __shfl_sync(0xffffffffu, h0u, baseL);
                float a1 = __shfl_sync(0xffffffffu, h0u, baseL + 1);
                float a2 = __shfl_sync(0xffffffffu, h0u, baseL + 2);
                float a3 = __shfl_sync(0xffffffffu, h0u, baseL + 3);
                float a4 = __shfl_sync(0xffffffffu, h0u, baseL + 4);
                h0v[0] = pack2(a0, a0);
                h0v[1] = pack2(a1, a1);
                h0v[2] = pack2(a2, a2);
                h0v[3] = pack2(a3, a3);
                h0v[4] = pack2(a4, a4);
            }

            // ---- layer 1: only the 5-fma2 Wih1@h0 half is serial now ----
            u64 gc = ga1p0;
            u64 gd = ga1p1;
            #pragma unroll
            for (int k = 0; k < HID_N; ++k) {
                gc = fma2(w1[0][1 + k], h0v[k], gc);
                gd = fma2(w1[1][1 + k], h0v[k], gd);
            }
            // ---- layer 1 activation ----
            float h1u;
            {
                float iv, fv, gv, ov, ig, fg;
                unpack2(gc, iv, fv);
                float ti = tanh_fast(iv), tf = tanh_fast(fv);
                unpack2(fma2(pack2(ti, tf), HALF2, HALF2), ig, fg);
                unpack2(gd, gv, ov);
                float gg = tanh_fast(gv);
                float og = fmaf(0.5f, tanh_fast(ov), 0.5f);
                float c  = fmaf(fg, c1, ig * gg);
                c1 = c;
                h1u = og * tanh_fast(c);
            }
            // ---- folded head: own unit only (weight from float4 register) ----
            accS = fmaf(h1u, wfs, accS);

            // ---- exchange full h1 ----
            {
                float a0 = __shfl_sync(0xffffffffu, h1u, baseL);
                float a1 = __shfl_sync(0xffffffffu, h1u, baseL + 1);
                float a2 = __shfl_sync(0xffffffffu, h1u, baseL + 2);
                float a3 = __shfl_sync(0xffffffffu, h1u, baseL + 3);
                float a4 = __shfl_sync(0xffffffffu, h1u, baseL + 4);
                h1v[0] = pack2(a0, a0);
                h1v[1] = pack2(a1, a1);
                h1v[2] = pack2(a2, a2);
                h1v[3] = pack2(a3, a3);
                h1v[4] = pack2(a4, a4);
            }

            // ---- PIPELINE: recurrent half of next step's layer-1 gates ----
            ga1p0 = w1[0][0];
            ga1p1 = w1[1][0];
            #pragma unroll
            for (int k = 0; k < HID_N; ++k) {
                ga1p0 = fma2(w1[0][6 + k], h1v[k], ga1p0);
                ga1p1 = fma2(w1[1][6 + k], h1v[k], ga1p1);
            }
        }
    }

    // ---- combine the 5 role partials; role 0 of each valid group writes ----
    float p0 = __shfl_sync(0xffffffffu, accS, baseL);
    float p1 = __shfl_sync(0xffffffffu, accS, baseL + 1);
    float p2 = __shfl_sync(0xffffffffu, accS, baseL + 2);
    float p3 = __shfl_sync(0xffffffffu, accS, baseL + 3);
    float p4 = __shfl_sync(0xffffffffu, accS, baseL + 4);
    if (u == 0 && valid)
        out[e] = ((p0 + p1) + (p2 + p3)) + p4 + g_beff;
}

// ---------------------------------------------------------------------------
// Harness entry. Inputs in metadata order:
// x, Wih0, Whh0, bih0, bhh0, Wih1, Whh1, bih1, bhh1, W1, b1, W2, b2
// ---------------------------------------------------------------------------
extern "C" void kernel_launch(void* const* d_in, const int* in_sizes, int n_in,
                              void* d_out, int out_size)
{
    const float* x    = (const float*)d_in[0];
    const float* Wih0 = (const float*)d_in[1];
    const float* Whh0 = (const float*)d_in[2];
    const float* bih0 = (const float*)d_in[3];
    const float* bhh0 = (const float*)d_in[4];
    const float* Wih1 = (const float*)d_in[5];
    const float* Whh1 = (const float*)d_in[6];
    const float* bih1 = (const float*)d_in[7];
    const float* bhh1 = (const float*)d_in[8];
    const float* W1   = (const float*)d_in[9];
    const float* b1   = (const float*)d_in[10];
    const float* W2   = (const float*)d_in[11];
    const float* b2   = (const float*)d_in[12];
    float* out = (float*)d_out;

    weff_kernel<<<(FLAT_N + 511) / 512, 512>>>(W1, b1, W2, b2);

    // 5 threads/element, 640-thread blocks (20 warps = 5/SMSP), 120 elems/block
    const int nblocks = (BATCH_N + EPB - 1) / EPB;   // 137 <= 148 SMs, one wave
    lstm_fused_kernel<<<nblocks, TPB>>>(x, Wih0, Whh0, bih0, bhh0,
                                        Wih1, Whh1, bih1, bhh1, out);
}

// round 14
// speedup vs baseline: 1.2978x; 1.0812x over previous
#include <cuda_runtime.h>
#include <cstddef>

#define BATCH_N 16384
#define SEQ_N   512
#define HID_N   5
#define FLAT_N  2560        // SEQ_N*HID_N
#define TPB     640         // 20 warps = 5 warps/SMSP
#define EPW     6           // elements per warp (lanes 0-29; 30,31 idle)
#define EPB     120         // elements per block = 20 warps * 6

// Collapsed linear head: Weff = W2 @ W1 (1 x 2560), beff = W2@b1 + b2
__device__ float g_Weff[FLAT_N];
__device__ float g_beff;

// ---------------------------------------------------------------------------
// Kernel 1: collapse the two linear layers (no nonlinearity between them).
// ---------------------------------------------------------------------------
__global__ void weff_kernel(const float* __restrict__ W1,
                            const float* __restrict__ b1,
                            const float* __restrict__ W2,
                            const float* __restrict__ b2)
{
    int j = blockIdx.x * blockDim.x + threadIdx.x;
    if (j < FLAT_N) {
        float acc = 0.0f;
        #pragma unroll 8
        for (int k = 0; k < 512; ++k)
            acc = fmaf(W2[k], W1[(size_t)k * FLAT_N + j], acc);
        g_Weff[j] = acc;
    }
    if (j == 0) {
        float acc = b2[0];
        for (int k = 0; k < 512; ++k)
            acc = fmaf(W2[k], b1[k], acc);
        g_beff = acc;
    }
}

// ---------------------------------------------------------------------------
// Packed f32x2 + fast-activation primitives
// ---------------------------------------------------------------------------
typedef unsigned long long u64;

__device__ __forceinline__ u64 pack2(float lo, float hi) {
    u64 r; asm("mov.b64 %0, {%1, %2};" : "=l"(r) : "f"(lo), "f"(hi)); return r;
}
__device__ __forceinline__ void unpack2(u64 v, float& lo, float& hi) {
    asm("mov.b64 {%0, %1}, %2;" : "=f"(lo), "=f"(hi) : "l"(v));
}
__device__ __forceinline__ u64 fma2(u64 a, u64 b, u64 c) {
    u64 d; asm("fma.rn.f32x2 %0, %1, %2, %3;" : "=l"(d) : "l"(a), "l"(b), "l"(c)); return d;
}
__device__ __forceinline__ float tanh_fast(float x) {
    float y; asm("tanh.approx.f32 %0, %1;" : "=f"(y) : "f"(x)); return y;
}

// ---------------------------------------------------------------------------
// Kernel 2: FIVE threads per batch element; thread role u owns hidden unit u
// in both layers. Fully software-pipelined recurrence:
//   * ga0(s+1) = B0 + Wih0 x(s+1) + Whh0@h0(s)  computed right after the h0
//     exchange of step s (overlaps layer 1 + activations of step s)
//   * ga1p(s+1) = B1 + Whh1@h1(s)  computed right after the h1 exchange
//   -> the loop-carried serial path is only act0 -> shfl -> (short chains)
// Layer-1 weights (22 u64) register-resident; layer-0 via padded LDS.128.
// Head weights: one scalar broadcast LDS per step (saves regs vs float4).
// ---------------------------------------------------------------------------
__global__ void __launch_bounds__(TPB, 1)
lstm_fused_kernel(const float* __restrict__ x,
                  const float* __restrict__ Wih0, const float* __restrict__ Whh0,
                  const float* __restrict__ bih0, const float* __restrict__ bhh0,
                  const float* __restrict__ Wih1, const float* __restrict__ Whh1,
                  const float* __restrict__ bih1, const float* __restrict__ bhh1,
                  float* __restrict__ out)
{
    // L0: role stride 18 u64 (=144B, conflict-free); pair p at +8p, slots:
    //   0=B, 1=Wih, 2..6=Whh c0..c4, 7=pad
    __shared__ __align__(16) u64 sL0[5 * 18];
    // L1 staging (copied to regs): [role][pair][0=B,1..5=Wih1,6..10=Whh1]
    __shared__ __align__(16) u64 sL1[5][2][11];
    // Head weights: sWf[u*513 + s] = Weff[5s+u]; stride 513 -> distinct banks
    __shared__ float sWf[5 * (SEQ_N + 1)];

    const int t = threadIdx.x;

    // ---- build tables (10 builder threads: role u, pair p) ----
    if (t < 10) {
        const int u = t >> 1, p = t & 1;
        const int rowA = (p == 0) ? u : 10 + u;        // i or g
        const int rowB = (p == 0) ? 5 + u : 15 + u;    // f or o
        const float sA = (p == 0) ? 0.5f : 1.0f;       // i scaled, g not
        const float sB = 0.5f;                          // f, o scaled

        u64* L0 = &sL0[u * 18 + p * 8];
        L0[0] = pack2(sA * (bih0[rowA] + bhh0[rowA]), sB * (bih0[rowB] + bhh0[rowB]));
        L0[1] = pack2(sA * Wih0[rowA], sB * Wih0[rowB]);
        sL1[u][p][0] = pack2(sA * (bih1[rowA] + bhh1[rowA]), sB * (bih1[rowB] + bhh1[rowB]));
        #pragma unroll
        for (int k = 0; k < HID_N; ++k) {
            L0[2 + k]        = pack2(sA * Whh0[rowA * HID_N + k], sB * Whh0[rowB * HID_N + k]);
            sL1[u][p][1 + k] = pack2(sA * Wih1[rowA * HID_N + k], sB * Wih1[rowB * HID_N + k]);
            sL1[u][p][6 + k] = pack2(sA * Whh1[rowA * HID_N + k], sB * Whh1[rowB * HID_N + k]);
        }
        L0[7] = 0ull;
    }
    for (int i = t; i < HID_N * SEQ_N; i += TPB) {
        const int u = i / SEQ_N, s = i - u * SEQ_N;
        sWf[u * (SEQ_N + 1) + s] = g_Weff[5 * s + u];
    }
    __syncthreads();

    const int lane  = t & 31;
    const int warp  = t >> 5;
    const int group = lane / 5;                 // 0..5 real, 6 = lanes 30,31
    const int u     = lane - group * 5;         // role / owned unit
    const int baseL = group * 5;

    const int  e_raw = blockIdx.x * EPB + warp * EPW + group;
    const bool valid = (group < EPW) && (e_raw < BATCH_N);
    const int  e     = valid ? e_raw : 0;

    const float4* __restrict__ xr4 = (const float4*)(x + (size_t)e * SEQ_N);
    const u64*   __restrict__ L0   = &sL0[u * 18];
    const float* __restrict__ Wfr  = &sWf[u * (SEQ_N + 1)];

    // ---- hoist layer-1 weights into registers (22 u64 = 44 regs) ----
    u64 w1[2][11];
    #pragma unroll
    for (int p = 0; p < 2; ++p)
        #pragma unroll
        for (int k = 0; k < 11; ++k)
            w1[p][k] = sL1[u][p][k];

    const u64 HALF2 = pack2(0.5f, 0.5f);

    u64 h0v[HID_N], h1v[HID_N];                 // broadcast-packed full h
    float c0 = 0.f, c1 = 0.f;                   // own unit's cell state
    #pragma unroll
    for (int k = 0; k < HID_N; ++k) { h0v[k] = 0ull; h1v[k] = 0ull; }

    float accS = 0.0f;

    // ---- prologue: pipeline registers ----
    float4 xq = __ldg(&xr4[0]);
    // ga0 for step 0 (h0v == 0): B0 + Wih0*x(0)
    u64 ga0a, ga0b;
    {
        const u64 xx = pack2(xq.x, xq.x);
        ga0a = fma2(L0[1], xx, L0[0]);
        ga0b = fma2(L0[9], xx, L0[8]);
        #pragma unroll
        for (int k = 0; k < HID_N; ++k) {
            ga0a = fma2(L0[2 + k],  h0v[k], ga0a);
            ga0b = fma2(L0[10 + k], h0v[k], ga0b);
        }
    }
    // ga1p for step 0 (h1v == 0): B1
    u64 ga1p0 = w1[0][0];
    u64 ga1p1 = w1[1][0];

    #pragma unroll 1
    for (int s4 = 0; s4 < SEQ_N / 4; ++s4) {
        float4 xq_next;
        if (s4 + 1 < SEQ_N / 4) xq_next = __ldg(&xr4[s4 + 1]);
        else                    xq_next = make_float4(0.f, 0.f, 0.f, 0.f);

        #pragma unroll
        for (int su = 0; su < 4; ++su) {
            const int s = 4 * s4 + su;
            // x for step s+1 (dummy past the end; result discarded)
            const float xn = (su == 0) ? xq.y : (su == 1) ? xq.z
                           : (su == 2) ? xq.w : xq_next.x;

            // ---- layer 0 activation for step s (from pipelined ga0) ----
            float h0u;
            {
                float iv, fv, gv, ov, ig, fg;
                unpack2(ga0a, iv, fv);
                float ti = tanh_fast(iv), tf = tanh_fast(fv);
                unpack2(fma2(pack2(ti, tf), HALF2, HALF2), ig, fg);
                unpack2(ga0b, gv, ov);
                float gg = tanh_fast(gv);
                float og = fmaf(0.5f, tanh_fast(ov), 0.5f);
                float c  = fmaf(fg, c0, ig * gg);
                c0 = c;
                h0u = og * tanh_fast(c);
            }
            // ---- exchange full h0: 5 computed-lane shfls ----
            {
                float a0 = __shfl_sync(0xffffffffu, h0u, baseL);
                float a1 = __shfl_sync(0xffffffffu, h0u, baseL + 1);
                float a2 = __shfl_sync(0xffffffffu, h0u, baseL + 2);
                float a3 = __shfl_sync(0xffffffffu, h0u, baseL + 3);
                float a4 = __shfl_sync(0xffffffffu, h0u, baseL + 4);
                h0v[0] = pack2(a0, a0);
                h0v[1] = pack2(a1, a1);
                h0v[2] = pack2(a2, a2);
                h0v[3] = pack2(a3, a3);
                h0v[4] = pack2(a4, a4);
            }

            // ---- layer 1: only the 5-fma2 Wih1@h0 half is serial ----
            u64 gc = ga1p0;
            u64 gd = ga1p1;
            #pragma unroll
            for (int k = 0; k < HID_N; ++k) {
                gc = fma2(w1[0][1 + k], h0v[k], gc);
                gd = fma2(w1[1][1 + k], h0v[k], gd);
            }

            // ---- PIPELINE: full layer-0 gates for step s+1 (needs only
            //      h0v(s) + x(s+1); overlaps act1 + head below) ----
            {
                const u64 xx = pack2(xn, xn);
                ga0a = fma2(L0[1], xx, L0[0]);
                ga0b = fma2(L0[9], xx, L0[8]);
                #pragma unroll
                for (int k = 0; k < HID_N; ++k) {
                    ga0a = fma2(L0[2 + k],  h0v[k], ga0a);
                    ga0b = fma2(L0[10 + k], h0v[k], ga0b);
                }
            }

            // ---- layer 1 activation ----
            float h1u;
            {
                float iv, fv, gv, ov, ig, fg;
                unpack2(gc, iv, fv);
                float ti = tanh_fast(iv), tf = tanh_fast(fv);
                unpack2(fma2(pack2(ti, tf), HALF2, HALF2), ig, fg);
                unpack2(gd, gv, ov);
                float gg = tanh_fast(gv);
                float og = fmaf(0.5f, tanh_fast(ov), 0.5f);
                float c  = fmaf(fg, c1, ig * gg);
                c1 = c;
                h1u = og * tanh_fast(c);
            }
            // ---- folded head: own unit only (broadcast scalar LDS) ----
            accS = fmaf(h1u, Wfr[s], accS);

            // ---- exchange full h1 ----
            {
                float a0 = __shfl_sync(0xffffffffu, h1u, baseL);
                float a1 = __shfl_sync(0xffffffffu, h1u, baseL + 1);
                float a2 = __shfl_sync(0xffffffffu, h1u, baseL + 2);
                float a3 = __shfl_sync(0xffffffffu, h1u, baseL + 3);
                float a4 = __shfl_sync(0xffffffffu, h1u, baseL + 4);
                h1v[0] = pack2(a0, a0);
                h1v[1] = pack2(a1, a1);
                h1v[2] = pack2(a2, a2);
                h1v[3] = pack2(a3, a3);
                h1v[4] = pack2(a4, a4);
            }

            // ---- PIPELINE: recurrent half of next step's layer-1 gates ----
            ga1p0 = w1[0][0];
            ga1p1 = w1[1][0];
            #pragma unroll
            for (int k = 0; k < HID_N; ++k) {
                ga1p0 = fma2(w1[0][6 + k], h1v[k], ga1p0);
                ga1p1 = fma2(w1[1][6 + k], h1v[k], ga1p1);
            }
        }
        xq = xq_next;
    }

    // ---- combine the 5 role partials; role 0 of each valid group writes ----
    float p0 = __shfl_sync(0xffffffffu, accS, baseL);
    float p1 = __shfl_sync(0xffffffffu, accS, baseL + 1);
    float p2 = __shfl_sync(0xffffffffu, accS, baseL + 2);
    float p3 = __shfl_sync(0xffffffffu, accS, baseL + 3);
    float p4 = __shfl_sync(0xffffffffu, accS, baseL + 4);
    if (u == 0 && valid)
        out[e] = ((p0 + p1) + (p2 + p3)) + p4 + g_beff;
}

// ---------------------------------------------------------------------------
// Harness entry. Inputs in metadata order:
// x, Wih0, Whh0, bih0, bhh0, Wih1, Whh1, bih1, bhh1, W1, b1, W2, b2
// ---------------------------------------------------------------------------
extern "C" void kernel_launch(void* const* d_in, const int* in_sizes, int n_in,
                              void* d_out, int out_size)
{
    const float* x    = (const float*)d_in[0];
    const float* Wih0 = (const float*)d_in[1];
    const float* Whh0 = (const float*)d_in[2];
    const float* bih0 = (const float*)d_in[3];
    const float* bhh0 = (const float*)d_in[4];
    const float* Wih1 = (const float*)d_in[5];
    const float* Whh1 = (const float*)d_in[6];
    const float* bih1 = (const float*)d_in[7];
    const float* bhh1 = (const float*)d_in[8];
    const float* W1   = (const float*)d_in[9];
    const float* b1   = (const float*)d_in[10];
    const float* W2   = (const float*)d_in[11];
    const float* b2   = (const float*)d_in[12];
    float* out = (float*)d_out;

    weff_kernel<<<(FLAT_N + 511) / 512, 512>>>(W1, b1, W2, b2);

    // 5 threads/element, 640-thread blocks (20 warps = 5/SMSP), 120 elems/block
    const int nblocks = (BATCH_N + EPB - 1) / EPB;   // 137 <= 148 SMs, one wave
    lstm_fused_kernel<<<nblocks, TPB>>>(x, Wih0, Whh0, bih0, bhh0,
                                        Wih1, Whh1, bih1, bhh1, out);
}